// round 1
// baseline (speedup 1.0000x reference)
#include <cuda_runtime.h>
#include <math.h>
#include <stdint.h>

#define BATCH 64
#define SEQ   512
#define DIN   1024
#define DENSE 1024
#define HID   768
#define G4    (4*HID)    // 3072
#define E2    (2*HID)    // 1536
#define NINT  60
#define MT    (BATCH*SEQ) // 32768

// ---------------- static device buffers (no runtime allocation) ----------------
__device__ float d_reg [(size_t)MT * DENSE];
__device__ float d_xpf [(size_t)MT * G4];
__device__ float d_xpb [(size_t)MT * G4];
__device__ float d_enc0[(size_t)MT * E2];
__device__ float d_enc1[(size_t)MT * E2];
__device__ float d_whT [4][(size_t)G4 * HID];   // [layer*2+dir][n][k]
__device__ float d_h   [2][2][BATCH][HID];      // [parity][dir][b][k]
__device__ float d_scores[MT];
__device__ float d_attn  [MT];
__device__ float d_ctx [BATCH * E2];
__device__ float d_ctx2[BATCH * E2];
__device__ unsigned d_bar_cnt = 0;
__device__ volatile unsigned d_bar_gen = 0;

__device__ __forceinline__ float* buf_sel(int s) {
    switch (s) {
        case 0: return d_reg;
        case 1: return d_xpf;
        case 2: return d_xpb;
        case 3: return d_enc0;
        default: return d_enc1;
    }
}

// ---------------- software grid barrier (all blocks co-resident) ----------------
__device__ __forceinline__ void grid_bar() {
    __syncthreads();
    if (threadIdx.x == 0) {
        unsigned gen = d_bar_gen;          // read phase BEFORE arriving
        __threadfence();
        unsigned arrived = atomicAdd(&d_bar_cnt, 1u);
        if (arrived == gridDim.x - 1) {
            d_bar_cnt = 0;
            __threadfence();
            d_bar_gen = gen + 1;
        } else {
            while (d_bar_gen == gen) { }
        }
        __threadfence();
    }
    __syncthreads();
}

// ---------------- fp32 SGEMM: C[M,N] = act(A[M,K] @ W[K,N] + bias) ----------------
// 128x128 tile, Kt=8, 256 threads, 8x8 micro-tile (4+4 split). All dims multiples of 128/8.
template <bool TANH>
__global__ void __launch_bounds__(256) sgemm_bias(
    const float* __restrict__ Aext, int aSel,
    const float* __restrict__ W, const float* __restrict__ bias,
    int cSel, int M, int N, int K)
{
    const float* A = (aSel < 0) ? Aext : buf_sel(aSel);
    float* C = buf_sel(cSel);

    __shared__ float As[8][128];
    __shared__ float Bs[8][128];

    const int bm = blockIdx.y * 128;
    const int bn = blockIdx.x * 128;
    const int tid = threadIdx.x;
    const int a_m = tid >> 1;
    const int a_k = (tid & 1) * 4;
    const int b_k = tid >> 5;
    const int b_n = (tid & 31) * 4;
    const int tx = tid & 15;
    const int ty = tid >> 4;

    float acc[8][8];
#pragma unroll
    for (int i = 0; i < 8; i++)
#pragma unroll
        for (int j = 0; j < 8; j++) acc[i][j] = 0.f;

    for (int k0 = 0; k0 < K; k0 += 8) {
        float4 av = *(const float4*)&A[(size_t)(bm + a_m) * K + k0 + a_k];
        As[a_k + 0][a_m] = av.x;
        As[a_k + 1][a_m] = av.y;
        As[a_k + 2][a_m] = av.z;
        As[a_k + 3][a_m] = av.w;
        *(float4*)&Bs[b_k][b_n] = *(const float4*)&W[(size_t)(k0 + b_k) * N + bn + b_n];
        __syncthreads();
#pragma unroll
        for (int kk = 0; kk < 8; kk++) {
            float ar[8], br[8];
            *(float4*)&ar[0] = *(const float4*)&As[kk][ty * 4];
            *(float4*)&ar[4] = *(const float4*)&As[kk][64 + ty * 4];
            *(float4*)&br[0] = *(const float4*)&Bs[kk][tx * 4];
            *(float4*)&br[4] = *(const float4*)&Bs[kk][64 + tx * 4];
#pragma unroll
            for (int i = 0; i < 8; i++)
#pragma unroll
                for (int j = 0; j < 8; j++)
                    acc[i][j] = fmaf(ar[i], br[j], acc[i][j]);
        }
        __syncthreads();
    }

#pragma unroll
    for (int hm = 0; hm < 2; hm++) {
#pragma unroll
        for (int i = 0; i < 4; i++) {
            int r = bm + hm * 64 + ty * 4 + i;
            int ri = hm * 4 + i;
#pragma unroll
            for (int hn = 0; hn < 2; hn++) {
                int cb = bn + hn * 64 + tx * 4;
                float4 v;
                v.x = acc[ri][hn * 4 + 0] + (bias ? bias[cb + 0] : 0.f);
                v.y = acc[ri][hn * 4 + 1] + (bias ? bias[cb + 1] : 0.f);
                v.z = acc[ri][hn * 4 + 2] + (bias ? bias[cb + 2] : 0.f);
                v.w = acc[ri][hn * 4 + 3] + (bias ? bias[cb + 3] : 0.f);
                if (TANH) { v.x = tanhf(v.x); v.y = tanhf(v.y); v.z = tanhf(v.z); v.w = tanhf(v.w); }
                *(float4*)&C[(size_t)r * N + cb] = v;
            }
        }
    }
}

// ---------------- Wh transpose: Wt[n][k] = W[k][n], K=768, N=3072 ----------------
__global__ void transpose_wh(const float* __restrict__ W, int widx) {
    __shared__ float tile[32][33];
    float* Wt = d_whT[widx];
    int k0 = blockIdx.y * 32, n0 = blockIdx.x * 32;
    int tx = threadIdx.x, ty = threadIdx.y;
    for (int i = ty; i < 32; i += 8)
        tile[i][tx] = W[(size_t)(k0 + i) * G4 + n0 + tx];
    __syncthreads();
    for (int i = ty; i < 32; i += 8)
        Wt[(size_t)(n0 + i) * HID + k0 + tx] = tile[tx][i];
}

// ---------------- persistent BiLSTM layer (fwd+bwd), 128 blocks x 192 threads ----------------
// Block = (dir, 16-batch tile, 48-j tile). Thread = 4 batches x (j = jbase+tx) x 4 gates.
// Cell state c lives in registers for all 512 steps; h ping-pongs in global.
__global__ void __launch_bounds__(192, 1) lstm_layer(int layer, const int* __restrict__ lens) {
    __shared__ float Hs[16][HID];  // 48KB: h snapshot for this block's 16 batches

    const int tid = threadIdx.x;
    const int dir = blockIdx.x >> 6;      // 0 fwd, 1 bwd
    const int rem = blockIdx.x & 63;
    const int b0 = (rem >> 4) * 16;       // batch tile base
    const int jbase = (rem & 15) * 48;    // j tile base
    const int tx = tid % 48;
    const int ty = tid / 48;              // 0..3
    const int j = jbase + tx;
    const int bloc0 = ty * 4;

    const float* xp = (layer == 0) ? (dir ? d_xpb : d_xpf) : (dir ? d_xpb : d_xpf);
    // note: xp buffers are re-filled per layer; same storage
    const float* whT = d_whT[layer * 2 + dir];
    float* enc = layer ? d_enc1 : d_enc0;

    int myb[4], myL[4];
#pragma unroll
    for (int bi = 0; bi < 4; bi++) {
        myb[bi] = b0 + bloc0 + bi;
        myL[bi] = lens[myb[bi]];
    }
    int maxL = max(max(myL[0], myL[1]), max(myL[2], myL[3]));

    // init h parity-0 (this block's slice) and register cell state
    for (int i = tid; i < 16 * 48; i += 192) {
        d_h[0][dir][b0 + (i / 48)][jbase + (i % 48)] = 0.f;
    }
    float c4[4] = {0.f, 0.f, 0.f, 0.f};
    grid_bar();

    const float* wr0 = whT + (size_t)(0 * HID + j) * HID;
    const float* wr1 = whT + (size_t)(1 * HID + j) * HID;
    const float* wr2 = whT + (size_t)(2 * HID + j) * HID;
    const float* wr3 = whT + (size_t)(3 * HID + j) * HID;

    for (int t = 0; t < SEQ; t++) {
        const int p = t & 1;
        // stage h snapshot (L2-coherent loads; other blocks wrote it last step)
        const float4* hsrc = (const float4*)&d_h[p][dir][b0][0];
        float4* hdst = (float4*)&Hs[0][0];
        for (int i = tid; i < (16 * HID) / 4; i += 192)
            hdst[i] = __ldcg(hsrc + i);
        __syncthreads();

        float acc[4][4];
#pragma unroll
        for (int bi = 0; bi < 4; bi++)
#pragma unroll
            for (int g = 0; g < 4; g++) acc[bi][g] = 0.f;

        if (t < maxL) {
#pragma unroll 2
            for (int k = 0; k < HID; k += 4) {
                float4 w0 = *(const float4*)(wr0 + k);
                float4 w1 = *(const float4*)(wr1 + k);
                float4 w2 = *(const float4*)(wr2 + k);
                float4 w3 = *(const float4*)(wr3 + k);
#pragma unroll
                for (int bi = 0; bi < 4; bi++) {
                    float4 hv = *(const float4*)&Hs[bloc0 + bi][k];
                    acc[bi][0] += hv.x * w0.x + hv.y * w0.y + hv.z * w0.z + hv.w * w0.w;
                    acc[bi][1] += hv.x * w1.x + hv.y * w1.y + hv.z * w1.z + hv.w * w1.w;
                    acc[bi][2] += hv.x * w2.x + hv.y * w2.y + hv.z * w2.z + hv.w * w2.w;
                    acc[bi][3] += hv.x * w3.x + hv.y * w3.y + hv.z * w3.z + hv.w * w3.w;
                }
            }
        }

#pragma unroll
        for (int bi = 0; bi < 4; bi++) {
            const int b = myb[bi];
            const int L = myL[bi];
            const bool alive = (t < L);
            const int src = dir ? (alive ? (L - 1 - t) : t) : t;  // fwd: always t
            float hold = Hs[bloc0 + bi][j];
            float hnew, outv;
            if (alive) {
                const float* xr = xp + ((size_t)b * SEQ + src) * G4;
                float zi = acc[bi][0] + xr[j];
                float zf = acc[bi][1] + xr[HID + j];
                float zg = acc[bi][2] + xr[2 * HID + j];
                float zo = acc[bi][3] + xr[3 * HID + j];
                float si = 1.f / (1.f + expf(-zi));
                float sf = 1.f / (1.f + expf(-zf));
                float so = 1.f / (1.f + expf(-zo));
                float nc = sf * c4[bi] + si * tanhf(zg);
                c4[bi] = nc;
                hnew = so * tanhf(nc);
                outv = hnew;
            } else {
                hnew = hold;   // carry h across ping-pong
                outv = 0.f;    // masked positions: write 0 (never used downstream)
            }
            d_h[p ^ 1][dir][b][j] = hnew;
            enc[((size_t)b * SEQ + src) * E2 + dir * HID + j] = outv;
        }
        grid_bar();
    }
}

// ---------------- attention tail ----------------
__global__ void scores_kernel(const float* __restrict__ we) {  // ekey lives in d_xpf
    const int warp = threadIdx.x >> 5, lane = threadIdx.x & 31;
    const size_t row = (size_t)blockIdx.x * 8 + warp;
    const float* r = d_xpf + row * E2;
    float s = 0.f;
    for (int k = lane; k < E2; k += 32) s += r[k] * we[k];
#pragma unroll
    for (int o = 16; o; o >>= 1) s += __shfl_down_sync(0xffffffffu, s, o);
    if (!lane) d_scores[row] = s;
}

__global__ void softmax_kernel(const int* __restrict__ lens) {
    __shared__ float red[512];
    const int b = blockIdx.x, t = threadIdx.x;
    const int L = lens[b];
    float v = (t < L) ? d_scores[b * SEQ + t] : -INFINITY;
    red[t] = v;
    __syncthreads();
    for (int s = 256; s > 0; s >>= 1) { if (t < s) red[t] = fmaxf(red[t], red[t + s]); __syncthreads(); }
    float m = red[0];
    __syncthreads();
    float e = (t < L) ? expf(v - m) : 0.f;
    red[t] = e;
    __syncthreads();
    for (int s = 256; s > 0; s >>= 1) { if (t < s) red[t] += red[t + s]; __syncthreads(); }
    d_attn[b * SEQ + t] = e / red[0];
}

__global__ void context_kernel() {
    const int b = blockIdx.y;
    const int h = blockIdx.x * 256 + threadIdx.x;
    float acc = 0.f;
    const float* a = d_attn + b * SEQ;
    const float* e = d_enc1 + (size_t)b * SEQ * E2 + h;
    for (int t = 0; t < SEQ; t++) acc += a[t] * e[(size_t)t * E2];
    d_ctx[b * E2 + h] = acc;
}

__global__ void post_kernel(const float* __restrict__ Wp, const float* __restrict__ bp) {
    const int b = blockIdx.y;
    const int n = blockIdx.x * 256 + threadIdx.x;
    float acc = bp[n];
    const float* c = d_ctx + b * E2;
    for (int k = 0; k < E2; k++) acc += c[k] * Wp[(size_t)k * E2 + n];
    d_ctx2[b * E2 + n] = acc;
}

__global__ void intents_kernel(const float* __restrict__ Wi, const float* __restrict__ bi, float* __restrict__ out) {
    const int b = blockIdx.x, n = threadIdx.x;
    if (n >= NINT) return;
    float acc = bi[n];
    const float* c = d_ctx2 + b * E2;
    for (int k = 0; k < E2; k++) acc += c[k] * Wi[k * NINT + n];
    out[b * NINT + n] = acc;
}

// ---------------- launch ----------------
extern "C" void kernel_launch(void* const* d_in, const int* in_sizes, int n_in,
                              void* d_out, int out_size) {
    const float* X    = (const float*)d_in[0];
    const int*   lens = (const int*)  d_in[1];
    const int s = (n_in >= 23) ? 3 : 2;  // skip is_test if present
    const float* W_reg  = (const float*)d_in[s + 0];
    const float* b_reg  = (const float*)d_in[s + 1];
    const float* Wi0f   = (const float*)d_in[s + 2];
    const float* Wh0f   = (const float*)d_in[s + 3];
    const float* b0f    = (const float*)d_in[s + 4];
    const float* Wi0b   = (const float*)d_in[s + 5];
    const float* Wh0b   = (const float*)d_in[s + 6];
    const float* b0b    = (const float*)d_in[s + 7];
    const float* Wi1f   = (const float*)d_in[s + 8];
    const float* Wh1f   = (const float*)d_in[s + 9];
    const float* b1f    = (const float*)d_in[s + 10];
    const float* Wi1b   = (const float*)d_in[s + 11];
    const float* Wh1b   = (const float*)d_in[s + 12];
    const float* b1b    = (const float*)d_in[s + 13];
    const float* W_keys = (const float*)d_in[s + 14];
    const float* W_en   = (const float*)d_in[s + 15];
    const float* W_post = (const float*)d_in[s + 16];
    const float* b_post = (const float*)d_in[s + 17];
    const float* W_int  = (const float*)d_in[s + 18];
    const float* b_int  = (const float*)d_in[s + 19];

    // 1) pre-transpose recurrent weights
    {
        dim3 g(G4 / 32, HID / 32), b(32, 8);
        transpose_wh<<<g, b>>>(Wh0f, 0);
        transpose_wh<<<g, b>>>(Wh0b, 1);
        transpose_wh<<<g, b>>>(Wh1f, 2);
        transpose_wh<<<g, b>>>(Wh1b, 3);
    }

    // 2) reg = X @ W_reg + b_reg
    sgemm_bias<false><<<dim3(DENSE / 128, MT / 128), 256>>>(X, -1, W_reg, b_reg, 0, MT, DENSE, DIN);

    // 3) layer-0 input projections (bias folded)
    sgemm_bias<false><<<dim3(G4 / 128, MT / 128), 256>>>(nullptr, 0, Wi0f, b0f, 1, MT, G4, DENSE);
    sgemm_bias<false><<<dim3(G4 / 128, MT / 128), 256>>>(nullptr, 0, Wi0b, b0b, 2, MT, G4, DENSE);

    // 4) layer-0 recurrence -> enc0
    lstm_layer<<<128, 192>>>(0, lens);

    // 5) layer-1 input projections
    sgemm_bias<false><<<dim3(G4 / 128, MT / 128), 256>>>(nullptr, 3, Wi1f, b1f, 1, MT, G4, E2);
    sgemm_bias<false><<<dim3(G4 / 128, MT / 128), 256>>>(nullptr, 3, Wi1b, b1b, 2, MT, G4, E2);

    // 6) layer-1 recurrence -> enc1
    lstm_layer<<<128, 192>>>(1, lens);

    // 7) ekey = tanh(enc1 @ W_keys)  (stored in d_xpf)
    sgemm_bias<true><<<dim3(E2 / 128, MT / 128), 256>>>(nullptr, 4, W_keys, nullptr, 1, MT, E2, E2);

    // 8) attention tail
    scores_kernel<<<MT / 8, 256>>>(W_en);
    softmax_kernel<<<BATCH, 512>>>(lens);
    context_kernel<<<dim3(E2 / 256, BATCH), 256>>>();
    post_kernel<<<dim3(E2 / 256, BATCH), 256>>>(W_post, b_post);
    intents_kernel<<<BATCH, 64>>>(W_int, b_int, (float*)d_out);
}